// round 15
// baseline (speedup 1.0000x reference)
#include <cuda_runtime.h>
#include <cuda_fp16.h>

#define BATCH  512
#define TSTEPS 256
#define IDIM   32
#define HDIM   128
#define GDIM   512                    // 4*H
#define MROWS  (BATCH * TSTEPS)       // 131072

// ---------------- scratch (static device globals: allocation-free) ----------
// g_xg layout: per (b, ts): 256 words; word u = half2(i,f) of unit u,
//              word 128+u = half2(g,o). Bias NOT included (added in rec1).
__device__ __half g_xg[(size_t)MROWS * GDIM];   // 128 MB fp16
__device__ float  g_h1last[BATCH * HDIM];       // last hidden of layer 1
__device__ __half g_whh[2 * GDIM * HDIM];       // fp16 w_hh0, w_hh1
__device__ __half g_wih0[GDIM * IDIM];          // fp16 w_ih0
__device__ __half g_wih1[GDIM * HDIM];          // fp16 w_ih1
__device__ __half g_xh[(size_t)BATCH * TSTEPS * IDIM];  // fp16 x
__device__ float  g_bsum0[GDIM], g_bsum1[GDIM]; // b_ih + b_hh

// ---------------- fast transcendentals ---------------------------------------
__device__ __forceinline__ float ex2f(float x) {
    float y; asm("ex2.approx.f32 %0, %1;" : "=f"(y) : "f"(x)); return y;
}
__device__ __forceinline__ float rcpf(float x) {
    float y; asm("rcp.approx.f32 %0, %1;" : "=f"(y) : "f"(x)); return y;
}
__device__ __forceinline__ float sigmf(float x) {
    return rcpf(1.0f + ex2f(-1.4426950408889634f * x));
}
__device__ __forceinline__ float tanhf_(float x) {
    return 2.0f * sigmf(2.0f * x) - 1.0f;
}

// ---------------- HMMA m16n8k16 fp16->fp32 -----------------------------------
__device__ __forceinline__ void hmma(float* c, const unsigned* a, unsigned b0, unsigned b1) {
    asm volatile("mma.sync.aligned.m16n8k16.row.col.f32.f16.f16.f32 "
        "{%0,%1,%2,%3}, {%4,%5,%6,%7}, {%8,%9}, {%0,%1,%2,%3};"
        : "+f"(c[0]), "+f"(c[1]), "+f"(c[2]), "+f"(c[3])
        : "r"(a[0]), "r"(a[1]), "r"(a[2]), "r"(a[3]), "r"(b0), "r"(b1));
}

__device__ __forceinline__ void ldsm4(unsigned* r, unsigned addr) {
    asm volatile("ldmatrix.sync.aligned.m8n8.x4.shared.b16 {%0,%1,%2,%3}, [%4];"
        : "=r"(r[0]), "=r"(r[1]), "=r"(r[2]), "=r"(r[3]) : "r"(addr));
}

// Gate-permuted A-fragments: warp owns all 4 gates of u-band u0..u0+7.
// mt=0 -> {i (+0), f (+128)}, mt=1 -> {g (+256), o (+384)}.
// After MMA: acc[0][j]=i(u, b=2tg+j), acc[0][2+j]=f, acc[1][j]=g, acc[1][2+j]=o.
template<int LD>
__device__ __forceinline__ void load_afrag_perm(unsigned afr[2][LD == 32 ? 2 : 8][4],
                                                const __half* W, int u0, int g, int tg) {
    const int NKT = (LD == 32) ? 2 : 8;
    #pragma unroll
    for (int mt = 0; mt < 2; mt++) {
        int rA = (mt * 256)       + u0 + g;   // i or g block
        int rB = (mt * 256 + 128) + u0 + g;   // f or o block
        #pragma unroll
        for (int kt = 0; kt < NKT; kt++) {
            int kb = kt * 16 + tg * 2;
            afr[mt][kt][0] = *(const unsigned*)&W[rA * LD + kb];
            afr[mt][kt][1] = *(const unsigned*)&W[rB * LD + kb];
            afr[mt][kt][2] = *(const unsigned*)&W[rA * LD + kb + 8];
            afr[mt][kt][3] = *(const unsigned*)&W[rB * LD + kb + 8];
        }
    }
}

// ---------------- K0: fp16 conversions + bias sums ---------------------------
__global__ void k_convert(const float* __restrict__ x,
                          const float* __restrict__ w_ih0, const float* __restrict__ w_hh0,
                          const float* __restrict__ b_ih0, const float* __restrict__ b_hh0,
                          const float* __restrict__ w_ih1, const float* __restrict__ w_hh1,
                          const float* __restrict__ b_ih1, const float* __restrict__ b_hh1) {
    int i = blockIdx.x * blockDim.x + threadIdx.x;
    if (i < BATCH * TSTEPS * IDIM) g_xh[i] = __float2half(x[i]);
    if (i < GDIM * HDIM) {
        g_whh[i]               = __float2half(w_hh0[i]);
        g_whh[GDIM * HDIM + i] = __float2half(w_hh1[i]);
        g_wih1[i]              = __float2half(w_ih1[i]);
    }
    if (i < GDIM * IDIM) g_wih0[i] = __float2half(w_ih0[i]);
    if (i < GDIM) {
        g_bsum0[i] = b_ih0[i] + b_hh0[i];
        g_bsum1[i] = b_ih1[i] + b_hh1[i];
    }
}

// Shuffle-redistribute: thread (g,tg) produced cells (u,2tg),(u,2tg+1) in
// (v0,v1); owner mapping b=tg pulls gate[j=tg&1] from lane (lane&~3)|(tg>>1).
__device__ __forceinline__ float gate_to_owner(float v0, float v1, int src, bool j1) {
    float a = __shfl_sync(0xffffffffu, v0, src);
    float b = __shfl_sync(0xffffffffu, v1, src);
    return j1 ? b : a;
}

// ---------------- K1: layer-0 recurrence FUSED with xg1 GEMM -----------------
// 128 CTAs x 512 threads; CTA owns 4 batch elems. Per step:
//   matmul0 (reg frags) -> shuffle -> cell -> STS h0_t -> barrier ->
//   xg1_t = W_ih1 @ h0_t  (A-frags via ldmatrix from smem, off critical path)
//   -> STG.32 (i,f)/(g,o) half2 pairs to g_xg. No g_h0, no gemmh kernel.
__global__ __launch_bounds__(512, 1) void k_rec0f() {
    extern __shared__ char smr[];
    __half* wih1s = (__half*)smr;                        // [512][136] 139264 B
    __half* xtile = (__half*)(smr + 139264);             // [256][4][40] 81920 B
    __half* zrow  = (__half*)(smr + 139264 + 81920);     // [40] zero row, 80 B
    __half* hT    = (__half*)(smr + 139264 + 82000);     // [2][8][136] 4352 B

    const int t = threadIdx.x;
    const int warp = t >> 5, lane = t & 31;
    const int g = lane >> 2, tg = lane & 3;
    const int u0 = warp * 8, u = u0 + g;
    const size_t cta_b = (size_t)blockIdx.x * 4;

    unsigned ah[2][8][4], ax[2][2][4];
    load_afrag_perm<HDIM>(ah, g_whh, u0, g, tg);
    load_afrag_perm<IDIM>(ax, g_wih0, u0, g, tg);

    // stage W_ih1 into smem (pitch 136 halves -> conflict-free ldmatrix)
    for (int i = t; i < 512 * 16; i += 512) {
        int r = i >> 4, q = i & 15;
        *(uint4*)&wih1s[r * 136 + q * 8] = *(const uint4*)&g_wih1[r * HDIM + q * 8];
    }
    // zero h buffers + zero row
    uint4 zz; zz.x = zz.y = zz.z = zz.w = 0u;
    for (int i = t; i < 2 * 8 * 136 / 8; i += 512) ((uint4*)hT)[i] = zz;
    if (t < 5) ((uint4*)zrow)[t] = zz;
    // stage x: [b][ts][32] -> xtile[ts][b][40]
    {
        uint4* xd = (uint4*)xtile;                       // row pitch 5 uint4
        const uint4* xsrc = (const uint4*)g_xh;
        for (int i = t; i < 256 * 4 * 4; i += 512) {
            int ts = i >> 4, b = (i >> 2) & 3, q = i & 3;
            xd[(ts * 4 + b) * 5 + q] = xsrc[(cta_b + b) * 1024 + ts * 4 + q];
        }
    }

    // per-lane ldmatrix row bases for the xg1 matmul (row indep. of kt)
    unsigned lmbase[2];
    {
        unsigned wbase = (unsigned)__cvta_generic_to_shared(wih1s);
        int lr = (lane & 7) + ((lane & 8) ? 128 : 0);
        int lk = (lane & 16) ? 16 : 0;                   // byte offset for k+8
        lmbase[0] = wbase + (unsigned)((0 * 256 + u0 + lr) * 136 * 2 + lk);
        lmbase[1] = wbase + (unsigned)((1 * 256 + u0 + lr) * 136 * 2 + lk);
    }

    const float bi = g_bsum0[u],       bf = g_bsum0[u + 128];
    const float bg = g_bsum0[u + 256], bo = g_bsum0[u + 384];
    const int  src = (lane & ~3) | (tg >> 1);
    const bool j1  = tg & 1;
    float cst = 0.f;
    __syncthreads();

    int cur = 0;
    for (int ts = 0; ts < TSTEPS; ts++) {
        // ---------- matmul0: gates0 = Whh0 @ h0_{t-1} + Wih0 @ x_t ----------
        float accA[2][4], accB[2][4];
        #pragma unroll
        for (int mt = 0; mt < 2; mt++)
            #pragma unroll
            for (int p = 0; p < 4; p++) { accA[mt][p] = 0.f; accB[mt][p] = 0.f; }

        const __half* xr = (g < 4) ? &xtile[(ts * 4 + g) * 40] : zrow;
        #pragma unroll
        for (int kt = 0; kt < 2; kt++) {
            unsigned b0 = *(const unsigned*)&xr[kt * 16 + tg * 2];
            unsigned b1 = *(const unsigned*)&xr[kt * 16 + tg * 2 + 8];
            hmma(accA[0], ax[0][kt], b0, b1);
            hmma(accA[1], ax[1][kt], b0, b1);
        }
        const __half* hc = hT + cur * (8 * 136);
        #pragma unroll
        for (int kt = 0; kt < 8; kt++) {
            unsigned b0 = *(const unsigned*)&hc[g * 136 + kt * 16 + tg * 2];
            unsigned b1 = *(const unsigned*)&hc[g * 136 + kt * 16 + tg * 2 + 8];
            float* dA = (kt < 4) ? accA[0] : accB[0];
            float* dB = (kt < 4) ? accA[1] : accB[1];
            hmma(dA, ah[0][kt], b0, b1);
            hmma(dB, ah[1][kt], b0, b1);
        }

        // ---------- shuffle to owner lane (b = tg); 1 cell/lane -------------
        float vi = gate_to_owner(accA[0][0] + accB[0][0], accA[0][1] + accB[0][1], src, j1);
        float vf = gate_to_owner(accA[0][2] + accB[0][2], accA[0][3] + accB[0][3], src, j1);
        float vg = gate_to_owner(accA[1][0] + accB[1][0], accA[1][1] + accB[1][1], src, j1);
        float vo = gate_to_owner(accA[1][2] + accB[1][2], accA[1][3] + accB[1][3], src, j1);

        __half* hn = hT + (cur ^ 1) * (8 * 136);
        {
            float gi = sigmf (vi + bi);
            float gf = sigmf (vf + bf);
            float gg = tanhf_(vg + bg);
            float go = sigmf (vo + bo);
            cst = gf * cst + gi * gg;
            float h = go * tanhf_(cst);
            hn[tg * 136 + u] = __float2half(h);
        }
        __syncthreads();

        // ---------- xg1_t = W_ih1 @ h0_t (off critical path, no barrier) ----
        {
            float xac[2][4];
            #pragma unroll
            for (int mt = 0; mt < 2; mt++)
                #pragma unroll
                for (int p = 0; p < 4; p++) xac[mt][p] = 0.f;

            #pragma unroll
            for (int kt = 0; kt < 8; kt++) {
                unsigned aw0[4], aw1[4];
                ldsm4(aw0, lmbase[0] + kt * 32);
                ldsm4(aw1, lmbase[1] + kt * 32);
                unsigned b0 = *(const unsigned*)&hn[g * 136 + kt * 16 + tg * 2];
                unsigned b1 = *(const unsigned*)&hn[g * 136 + kt * 16 + tg * 2 + 8];
                hmma(xac[0], aw0, b0, b1);
                hmma(xac[1], aw1, b0, b1);
            }
            if (tg < 2) {
                #pragma unroll
                for (int j = 0; j < 2; j++) {
                    int b = 2 * tg + j;
                    unsigned* wbase = (unsigned*)g_xg + ((cta_b + b) * TSTEPS + ts) * 256;
                    __half2 hif = __floats2half2_rn(xac[0][j], xac[0][2 + j]);  // (i,f)
                    __half2 hgo = __floats2half2_rn(xac[1][j], xac[1][2 + j]);  // (g,o)
                    wbase[u]       = *(unsigned*)&hif;
                    wbase[128 + u] = *(unsigned*)&hgo;
                }
            }
        }
        cur ^= 1;
    }
}

// ---------------- K2: layer-1 recurrence (gate-permuted + shuffle) -----------
// 128 CTAs x 512 threads; CTA owns 4 batch elems; xg double-buffered in smem.
// xg words: u -> (i,f), 128+u -> (g,o); bias bsum1 added here.
__global__ __launch_bounds__(512, 1) void k_rec1() {
    __shared__ __half xs[2][4 * 520];               // 8320 B
    __shared__ __half hT[2][8 * 136];               // 4352 B

    const int t = threadIdx.x;
    const int warp = t >> 5, lane = t & 31;
    const int g = lane >> 2, tg = lane & 3;
    const int u0 = warp * 8, u = u0 + g;
    const size_t cta_b = (size_t)blockIdx.x * 4;

    unsigned ah[2][8][4];
    load_afrag_perm<HDIM>(ah, g_whh + GDIM * HDIM, u0, g, tg);

    uint4 zz; zz.x = zz.y = zz.z = zz.w = 0u;
    for (int i = t; i < 2 * 8 * 136 / 8; i += 512) ((uint4*)hT)[i] = zz;

    // loader role (256 threads): batch lb = t>>6 (0..3), chunk lq = t&63
    const int lb = t >> 6, lq = t & 63;
    const bool loader = (t < 256);
    if (loader)
        *(uint4*)&xs[0][lb * 520 + lq * 8] =
            *(const uint4*)(g_xg + ((cta_b + lb) * TSTEPS) * GDIM + lq * 8);

    const float b1i = g_bsum1[u],       b1f = g_bsum1[u + 128];
    const float b1g = g_bsum1[u + 256], b1o = g_bsum1[u + 384];
    const int  src = (lane & ~3) | (tg >> 1);
    const bool j1  = tg & 1;
    float cst = 0.f;
    __syncthreads();

    int cur = 0;
    for (int ts = 0; ts < TSTEPS; ts++) {
        uint4 xpre = zz;
        if (loader && ts < TSTEPS - 1)
            xpre = *(const uint4*)(g_xg + ((cta_b + lb) * TSTEPS + ts + 1) * GDIM + lq * 8);

        float accA[2][4], accB[2][4];
        #pragma unroll
        for (int mt = 0; mt < 2; mt++)
            #pragma unroll
            for (int p = 0; p < 4; p++) { accA[mt][p] = 0.f; accB[mt][p] = 0.f; }

        const __half* hc = hT[cur];
        #pragma unroll
        for (int kt = 0; kt < 8; kt++) {
            unsigned b0 = *(const unsigned*)&hc[g * 136 + kt * 16 + tg * 2];
            unsigned b1 = *(const unsigned*)&hc[g * 136 + kt * 16 + tg * 2 + 8];
            float* dA = (kt < 4) ? accA[0] : accB[0];
            float* dB = (kt < 4) ? accA[1] : accB[1];
            hmma(dA, ah[0][kt], b0, b1);
            hmma(dB, ah[1][kt], b0, b1);
        }

        if (loader)
            *(uint4*)&xs[cur ^ 1][lb * 520 + lq * 8] = xpre;

        float vi = gate_to_owner(accA[0][0] + accB[0][0], accA[0][1] + accB[0][1], src, j1);
        float vf = gate_to_owner(accA[0][2] + accB[0][2], accA[0][3] + accB[0][3], src, j1);
        float vg = gate_to_owner(accA[1][0] + accB[1][0], accA[1][1] + accB[1][1], src, j1);
        float vo = gate_to_owner(accA[1][2] + accB[1][2], accA[1][3] + accB[1][3], src, j1);

        const unsigned* xw = (const unsigned*)&xs[cur][tg * 520];
        __half* hn = hT[cur ^ 1];
        {
            unsigned wif = xw[u], wgo = xw[128 + u];
            __half2 hif = *(__half2*)&wif, hgo = *(__half2*)&wgo;
            float gi = sigmf (vi + __low2float(hif)  + b1i);
            float gf = sigmf (vf + __high2float(hif) + b1f);
            float gg = tanhf_(vg + __low2float(hgo)  + b1g);
            float go = sigmf (vo + __high2float(hgo) + b1o);
            cst = gf * cst + gi * gg;
            float h = go * tanhf_(cst);
            hn[tg * 136 + u] = __float2half(h);
            if (ts == TSTEPS - 1)
                g_h1last[(cta_b + tg) * HDIM + u] = h;
        }
        __syncthreads();
        cur ^= 1;
    }
}

// ---------------- K3: FC head -------------------------------------------------
__global__ void k_fc(const float* __restrict__ w1, const float* __restrict__ b1,
                     const float* __restrict__ w2, const float* __restrict__ b2,
                     float* __restrict__ out) {
    __shared__ float red[2];
    int b = blockIdx.x, j = threadIdx.x;   // 64 threads
    const float* hv = g_h1last + b * HDIM;
    const float* wr = w1 + j * HDIM;
    float acc = b1[j];
    #pragma unroll 4
    for (int k = 0; k < HDIM; k++) acc += hv[k] * wr[k];
    float z = fmaxf(acc, 0.0f) * w2[j];
    #pragma unroll
    for (int off = 16; off > 0; off >>= 1) z += __shfl_down_sync(0xffffffffu, z, off);
    if ((j & 31) == 0) red[j >> 5] = z;
    __syncthreads();
    if (j == 0) out[b] = red[0] + red[1] + b2[0];
}

// ---------------- launch -----------------------------------------------------
extern "C" void kernel_launch(void* const* d_in, const int* in_sizes, int n_in,
                              void* d_out, int out_size) {
    const float* x     = (const float*)d_in[0];
    const float* w_ih0 = (const float*)d_in[1];
    const float* w_hh0 = (const float*)d_in[2];
    const float* b_ih0 = (const float*)d_in[3];
    const float* b_hh0 = (const float*)d_in[4];
    const float* w_ih1 = (const float*)d_in[5];
    const float* w_hh1 = (const float*)d_in[6];
    const float* b_ih1 = (const float*)d_in[7];
    const float* b_hh1 = (const float*)d_in[8];
    const float* fc1_w = (const float*)d_in[9];
    const float* fc1_b = (const float*)d_in[10];
    const float* fc2_w = (const float*)d_in[11];
    const float* fc2_b = (const float*)d_in[12];
    float* out = (float*)d_out;

    const int smem_rec0 = 139264 + 81920 + 80 + 4352;    // 225616
    cudaFuncSetAttribute(k_rec0f, cudaFuncAttributeMaxDynamicSharedMemorySize, smem_rec0);

    k_convert<<<(BATCH * TSTEPS * IDIM + 255) / 256, 256>>>(
        x, w_ih0, w_hh0, b_ih0, b_hh0, w_ih1, w_hh1, b_ih1, b_hh1);
    // layer 0 recurrence + fused xg1 GEMM (writes g_xg), 128 CTAs
    k_rec0f<<<BATCH / 4, 512, smem_rec0>>>();
    // layer-1 recurrence (writes g_h1last), 128 CTAs
    k_rec1<<<BATCH / 4, 512>>>();
    // FC head
    k_fc<<<BATCH, 64>>>(fc1_w, fc1_b, fc2_w, fc2_b, out);
}

// round 16
// speedup vs baseline: 1.2325x; 1.2325x over previous
#include <cuda_runtime.h>
#include <cuda_fp16.h>

#define BATCH  512
#define TSTEPS 256
#define IDIM   32
#define HDIM   128
#define GDIM   512                    // 4*H
#define MROWS  (BATCH * TSTEPS)       // 131072
#define GPITCH 10

typedef unsigned long long ull;

// ---------------- scratch (static device globals: allocation-free) ----------
__device__ __half g_xg[(size_t)MROWS * GDIM];   // 128 MB fp16, xg1
__device__ __half g_h0[(size_t)MROWS * HDIM];   // 32 MB fp16, layer-0 hidden
__device__ float  g_h1last[BATCH * HDIM];       // last hidden of layer 1
__device__ __half g_whh[2 * GDIM * HDIM];       // fp16 w_hh0, w_hh1
__device__ __half g_wih0[GDIM * IDIM];          // fp16 w_ih0
__device__ __half g_wih1[GDIM * HDIM];          // fp16 w_ih1
__device__ __half g_xh[(size_t)BATCH * TSTEPS * IDIM];  // fp16 x
__device__ float  g_bsum0[GDIM], g_bsum1[GDIM]; // b_ih + b_hh

// ---------------- fast transcendentals ---------------------------------------
__device__ __forceinline__ float ex2f(float x) {
    float y; asm("ex2.approx.f32 %0, %1;" : "=f"(y) : "f"(x)); return y;
}
__device__ __forceinline__ float rcpf(float x) {
    float y; asm("rcp.approx.f32 %0, %1;" : "=f"(y) : "f"(x)); return y;
}
__device__ __forceinline__ float sigmf(float x) {
    return rcpf(1.0f + ex2f(-1.4426950408889634f * x));
}
__device__ __forceinline__ float tanhf_(float x) {
    return 2.0f * sigmf(2.0f * x) - 1.0f;
}

// ---------------- HMMA m16n8k16 fp16->fp32 -----------------------------------
__device__ __forceinline__ void hmma(float* c, const unsigned* a, unsigned b0, unsigned b1) {
    asm volatile("mma.sync.aligned.m16n8k16.row.col.f32.f16.f16.f32 "
        "{%0,%1,%2,%3}, {%4,%5,%6,%7}, {%8,%9}, {%0,%1,%2,%3};"
        : "+f"(c[0]), "+f"(c[1]), "+f"(c[2]), "+f"(c[3])
        : "r"(a[0]), "r"(a[1]), "r"(a[2]), "r"(a[3]), "r"(b0), "r"(b1));
}

// A-fragments, natural row order: warp owns gate rows warp*32..warp*32+31.
template<int LD>
__device__ __forceinline__ void load_afrag(unsigned afr[2][LD == 32 ? 2 : 8][4],
                                           const __half* W, int warp, int g, int tg) {
    const int NKT = (LD == 32) ? 2 : 8;
    #pragma unroll
    for (int mt = 0; mt < 2; mt++) {
        int rbase = warp * 32 + mt * 16;
        #pragma unroll
        for (int kt = 0; kt < NKT; kt++) {
            int kb = kt * 16 + tg * 2;
            afr[mt][kt][0] = *(const unsigned*)&W[(rbase + g)     * LD + kb];
            afr[mt][kt][1] = *(const unsigned*)&W[(rbase + g + 8) * LD + kb];
            afr[mt][kt][2] = *(const unsigned*)&W[(rbase + g)     * LD + kb + 8];
            afr[mt][kt][3] = *(const unsigned*)&W[(rbase + g + 8) * LD + kb + 8];
        }
    }
}

// ---------------- K0: fp16 conversions + bias sums ---------------------------
__global__ void k_convert(const float* __restrict__ x,
                          const float* __restrict__ w_ih0, const float* __restrict__ w_hh0,
                          const float* __restrict__ b_ih0, const float* __restrict__ b_hh0,
                          const float* __restrict__ w_ih1, const float* __restrict__ w_hh1,
                          const float* __restrict__ b_ih1, const float* __restrict__ b_hh1) {
    int i = blockIdx.x * blockDim.x + threadIdx.x;
    if (i < BATCH * TSTEPS * IDIM) g_xh[i] = __float2half(x[i]);
    if (i < GDIM * HDIM) {
        g_whh[i]               = __float2half(w_hh0[i]);
        g_whh[GDIM * HDIM + i] = __float2half(w_hh1[i]);
        g_wih1[i]              = __float2half(w_ih1[i]);
    }
    if (i < GDIM * IDIM) g_wih0[i] = __float2half(w_ih0[i]);
    if (i < GDIM) {
        g_bsum0[i] = b_ih0[i] + b_hh0[i];
        g_bsum1[i] = b_ih1[i] + b_hh1[i];
    }
}

// ---------------- K1: layer-0 fused (input GEMM + recurrence) ----------------
// 128 CTAs x 512 threads; CTA owns 4 batch elems (MMA n-cols 4..7 ride zeros).
// gates -> smem (GPITCH), 2 barriers/step, elementwise 1 cell/thread. [R9 winner]
__global__ __launch_bounds__(512, 1) void k_rec0() {
    extern __shared__ char smr[];
    __half* xtile = (__half*)smr;                   // [ts][8][40] fp16, 163840 B
    float*  gates = (float*)(smr + 163840);         // [row][GPITCH] f32, 20480 B
    __half* hT    = (__half*)(smr + 184320);        // [2][8][136] fp16, 4352 B

    const int t = threadIdx.x;
    const int warp = t >> 5, lane = t & 31;
    const int g = lane >> 2, tg = lane & 3;
    const size_t cta_b = (size_t)blockIdx.x * 4;

    unsigned ah[2][8][4], ax[2][2][4];
    load_afrag<HDIM>(ah, g_whh, warp, g, tg);
    load_afrag<IDIM>(ax, g_wih0, warp, g, tg);

    // zero x tile (rows b=4..7 stay zero) and both h buffers
    uint4 zz; zz.x = zz.y = zz.z = zz.w = 0u;
    uint4* xd = (uint4*)xtile;                      // row pitch = 5 uint4
    for (int i = t; i < 256 * 8 * 5; i += 512) xd[i] = zz;
    for (int i = t; i < 2 * 8 * 136 / 8; i += 512) ((uint4*)hT)[i] = zz;
    __syncthreads();

    // stage x for 4 batches: [b][ts][32] -> xtile[ts][b][40]
    {
        const uint4* xs = (const uint4*)g_xh;
        for (int i = t; i < 256 * 4 * 4; i += 512) {
            int ts = i >> 4, b = (i >> 2) & 3, q = i & 3;
            xd[(ts * 8 + b) * 5 + q] = xs[(cta_b + b) * 1024 + ts * 4 + q];
        }
    }

    const int eb = t >> 7, u = t & 127;             // elementwise role
    const float bi = g_bsum0[u],       bf = g_bsum0[u + 128];
    const float bg = g_bsum0[u + 256], bo = g_bsum0[u + 384];
    float cstate = 0.f;
    __syncthreads();

    int cur = 0;
    for (int ts = 0; ts < TSTEPS; ts++) {
        float acc[2][4];
        #pragma unroll
        for (int mt = 0; mt < 2; mt++)
            #pragma unroll
            for (int p = 0; p < 4; p++) acc[mt][p] = 0.f;

        // x-part (K = 32)
        #pragma unroll
        for (int kt = 0; kt < 2; kt++) {
            unsigned b0 = *(const unsigned*)&xtile[(ts * 8 + g) * 40 + kt * 16 + tg * 2];
            unsigned b1 = *(const unsigned*)&xtile[(ts * 8 + g) * 40 + kt * 16 + tg * 2 + 8];
            hmma(acc[0], ax[0][kt], b0, b1);
            hmma(acc[1], ax[1][kt], b0, b1);
        }
        // h-part (K = 128)
        const __half* hc = hT + cur * (8 * 136);
        #pragma unroll
        for (int kt = 0; kt < 8; kt++) {
            unsigned b0 = *(const unsigned*)&hc[g * 136 + kt * 16 + tg * 2];
            unsigned b1 = *(const unsigned*)&hc[g * 136 + kt * 16 + tg * 2 + 8];
            hmma(acc[0], ah[0][kt], b0, b1);
            hmma(acc[1], ah[1][kt], b0, b1);
        }
        #pragma unroll
        for (int mt = 0; mt < 2; mt++) {
            int r = warp * 32 + mt * 16 + g;
            *(float2*)&gates[r * GPITCH + 2 * tg]       = make_float2(acc[mt][0], acc[mt][1]);
            *(float2*)&gates[(r + 8) * GPITCH + 2 * tg] = make_float2(acc[mt][2], acc[mt][3]);
        }
        __syncthreads();

        // elementwise: one cell (eb, u) per thread (eb and eb+2)
        __half* hn = hT + (cur ^ 1) * (8 * 136);
        {
            int base = u * GPITCH + eb;
            float gi = sigmf (gates[base]                + bi);
            float gf = sigmf (gates[base + 128 * GPITCH] + bf);
            float gg = tanhf_(gates[base + 256 * GPITCH] + bg);
            float go = sigmf (gates[base + 384 * GPITCH] + bo);
            cstate = gf * cstate + gi * gg;
            float h = go * tanhf_(cstate);
            hn[eb * 136 + u] = __float2half(h);
            g_h0[((cta_b + eb) * TSTEPS + ts) * HDIM + u] = __float2half(h);
        }
        {
            int b2 = eb + 2;
            int base = u * GPITCH + b2;
            float gi = sigmf (gates[base]                + bi);
            float gf = sigmf (gates[base + 128 * GPITCH] + bf);
            float gg = tanhf_(gates[base + 256 * GPITCH] + bg);
            float go = sigmf (gates[base + 384 * GPITCH] + bo);
            // second cell state lives in gates-free smem slot? No: keep in reg pair
            // (handled below via cst2)
            (void)gi; (void)gf; (void)gg; (void)go;
        }
        __syncthreads();
        cur ^= 1;
    }
}

// NOTE: k_rec0 above mistakenly sketched a second cell; the R9 winner maps
// 512 threads -> 512 cells (4 batches x 128 units) exactly once. The second
// block is dead code guarded by (void) casts; eb in 0..3 via t>>7 covers only
// b 0..3 (512 threads / 128 units = 4 batches). Correct as-is.

// ---------------- K2: xg1 = h0 @ w_ih1^T + bsum1 (HMMA, 16-row chunks) -------
__global__ __launch_bounds__(512, 1) void k_gemmh() {
    __shared__ __half atile[2][16 * 136];           // 2 x 4352 B
    __shared__ __half gtile[16 * 520];              // 16640 B
    const int t = threadIdx.x;
    const int warp = t >> 5, lane = t & 31;
    const int g = lane >> 2, tg = lane & 3;
    const size_t row0 = (size_t)blockIdx.x * 128;

    unsigned afr[2][8][4];
    float bb[2][2];
    #pragma unroll
    for (int mt = 0; mt < 2; mt++) {
        int rbase = warp * 32 + mt * 16;
        #pragma unroll
        for (int kt = 0; kt < 8; kt++) {
            int kb = kt * 16 + tg * 2;
            afr[mt][kt][0] = *(const unsigned*)&g_wih1[(rbase + g)     * HDIM + kb];
            afr[mt][kt][1] = *(const unsigned*)&g_wih1[(rbase + g + 8) * HDIM + kb];
            afr[mt][kt][2] = *(const unsigned*)&g_wih1[(rbase + g)     * HDIM + kb + 8];
            afr[mt][kt][3] = *(const unsigned*)&g_wih1[(rbase + g + 8) * HDIM + kb + 8];
        }
        bb[mt][0] = g_bsum1[rbase + g];
        bb[mt][1] = g_bsum1[rbase + g + 8];
    }

    // load chunk 0 (16 rows x 128 halves = 256 uint4)
    if (t < 256) {
        int r = t >> 4, q = t & 15;
        *(uint4*)&atile[0][r * 136 + q * 8] = *(const uint4*)(g_h0 + (row0 + r) * HDIM + q * 8);
    }
    __syncthreads();

    #pragma unroll 1
    for (int c = 0; c < 8; c++) {                   // 8 chunks of 16 rows
        int buf = c & 1;
        float acc[2][2][4];                         // [mt][ngroup][4]
        #pragma unroll
        for (int mt = 0; mt < 2; mt++)
            #pragma unroll
            for (int ng = 0; ng < 2; ng++)
                #pragma unroll
                for (int p = 0; p < 4; p++) acc[mt][ng][p] = 0.f;

        #pragma unroll
        for (int kt = 0; kt < 8; kt++) {
            unsigned b0a = *(const unsigned*)&atile[buf][g * 136 + kt * 16 + tg * 2];
            unsigned b1a = *(const unsigned*)&atile[buf][g * 136 + kt * 16 + tg * 2 + 8];
            unsigned b0b = *(const unsigned*)&atile[buf][(8 + g) * 136 + kt * 16 + tg * 2];
            unsigned b1b = *(const unsigned*)&atile[buf][(8 + g) * 136 + kt * 16 + tg * 2 + 8];
            hmma(acc[0][0], afr[0][kt], b0a, b1a);
            hmma(acc[0][1], afr[0][kt], b0b, b1b);
            hmma(acc[1][0], afr[1][kt], b0a, b1a);
            hmma(acc[1][1], afr[1][kt], b0b, b1b);
        }

        // prefetch next chunk (safe: buf^1 unused since 2 syncs ago)
        if (c < 7 && t < 256) {
            int r = t >> 4, q = t & 15;
            *(uint4*)&atile[buf ^ 1][r * 136 + q * 8] =
                *(const uint4*)(g_h0 + (row0 + (c + 1) * 16 + r) * HDIM + q * 8);
        }

        // epilogue: transpose through smem (gtile[n][gate])
        #pragma unroll
        for (int mt = 0; mt < 2; mt++) {
            int r = warp * 32 + mt * 16 + g;
            #pragma unroll
            for (int ng = 0; ng < 2; ng++) {
                int n0 = ng * 8 + 2 * tg;
                gtile[n0       * 520 + r]     = __float2half(acc[mt][ng][0] + bb[mt][0]);
                gtile[(n0 + 1) * 520 + r]     = __float2half(acc[mt][ng][1] + bb[mt][0]);
                gtile[n0       * 520 + r + 8] = __float2half(acc[mt][ng][2] + bb[mt][1]);
                gtile[(n0 + 1) * 520 + r + 8] = __float2half(acc[mt][ng][3] + bb[mt][1]);
            }
        }
        __syncthreads();

        // copy out: 16 rows x 512 halves = 1024 uint4, 2 per thread
        #pragma unroll
        for (int i = 0; i < 2; i++) {
            int idx = t + i * 512;
            int n = idx >> 6, off = (idx & 63) * 8;
            uint4 v = *(uint4*)&gtile[n * 520 + off];
            *(uint4*)(g_xg + (row0 + c * 16 + n) * GDIM + off) = v;
        }
        __syncthreads();
    }
}

// ---------------- K3: layer-1 recurrence (GPITCH gates) [R9 winner] ----------
__global__ __launch_bounds__(512, 1) void k_rec1() {
    __shared__ float  gates[GDIM * GPITCH];
    __shared__ __half hT[2][8 * 136];

    const int t = threadIdx.x;
    const int warp = t >> 5, lane = t & 31;
    const int g = lane >> 2, tg = lane & 3;
    const size_t cta_b = (size_t)blockIdx.x * 4;

    unsigned ah[2][8][4];
    load_afrag<HDIM>(ah, g_whh + GDIM * HDIM, warp, g, tg);

    uint4 zz; zz.x = zz.y = zz.z = zz.w = 0u;
    for (int i = t; i < 2 * 8 * 136 / 8; i += 512) ((uint4*)hT)[i] = zz;

    const int b = t >> 7, u = t & 127;
    float cstate = 0.f;
    const __half* xbase = g_xg + (cta_b + b) * ((size_t)TSTEPS * GDIM) + u;

    __half xc[4];
    xc[0] = xbase[0]; xc[1] = xbase[128]; xc[2] = xbase[256]; xc[3] = xbase[384];
    __syncthreads();

    int cur = 0;
    for (int ts = 0; ts < TSTEPS; ts++) {
        __half xn[4];
        if (ts < TSTEPS - 1) {
            const __half* xp = xbase + (size_t)(ts + 1) * GDIM;
            xn[0] = xp[0]; xn[1] = xp[128]; xn[2] = xp[256]; xn[3] = xp[384];
        }

        float acc[2][4];
        #pragma unroll
        for (int mt = 0; mt < 2; mt++)
            #pragma unroll
            for (int p = 0; p < 4; p++) acc[mt][p] = 0.f;

        const __half* hc = hT[cur];
        #pragma unroll
        for (int kt = 0; kt < 8; kt++) {
            unsigned b0 = *(const unsigned*)&hc[g * 136 + kt * 16 + tg * 2];
            unsigned b1 = *(const unsigned*)&hc[g * 136 + kt * 16 + tg * 2 + 8];
            hmma(acc[0], ah[0][kt], b0, b1);
            hmma(acc[1], ah[1][kt], b0, b1);
        }
        #pragma unroll
        for (int mt = 0; mt < 2; mt++) {
            int r = warp * 32 + mt * 16 + g;
            *(float2*)&gates[r * GPITCH + 2 * tg]       = make_float2(acc[mt][0], acc[mt][1]);
            *(float2*)&gates[(r + 8) * GPITCH + 2 * tg] = make_float2(acc[mt][2], acc[mt][3]);
        }
        __syncthreads();

        __half* hn = hT[cur ^ 1];
        {
            int base = u * GPITCH + b;
            float gi = sigmf (gates[base]                + __half2float(xc[0]));
            float gf = sigmf (gates[base + 128 * GPITCH] + __half2float(xc[1]));
            float gg = tanhf_(gates[base + 256 * GPITCH] + __half2float(xc[2]));
            float go = sigmf (gates[base + 384 * GPITCH] + __half2float(xc[3]));
            cstate = gf * cstate + gi * gg;
            float h = go * tanhf_(cstate);
            hn[b * 136 + u] = __float2half(h);
            if (ts == TSTEPS - 1)
                g_h1last[(cta_b + b) * HDIM + u] = h;
        }
        __syncthreads();

        xc[0] = xn[0]; xc[1] = xn[1]; xc[2] = xn[2]; xc[3] = xn[3];
        cur ^= 1;
    }
}

// ---------------- K4: FC head (ILP-fixed) -------------------------------------
__global__ void k_fc(const float* __restrict__ w1, const float* __restrict__ b1,
                     const float* __restrict__ w2, const float* __restrict__ b2,
                     float* __restrict__ out) {
    __shared__ float red[2];
    int b = blockIdx.x, j = threadIdx.x;   // 64 threads
    const float4* hv = (const float4*)(g_h1last + b * HDIM);
    const float4* wr = (const float4*)(w1 + j * HDIM);
    float a0 = 0.f, a1 = 0.f, a2 = 0.f, a3 = 0.f;
    #pragma unroll
    for (int k = 0; k < 32; k += 2) {
        float4 h0 = hv[k],     w0 = wr[k];
        float4 h1 = hv[k + 1], w1v = wr[k + 1];
        a0 += h0.x * w0.x + h0.y * w0.y;
        a1 += h0.z * w0.z + h0.w * w0.w;
        a2 += h1.x * w1v.x + h1.y * w1v.y;
        a3 += h1.z * w1v.z + h1.w * w1v.w;
    }
    float acc = ((a0 + a1) + (a2 + a3)) + b1[j];
    float z = fmaxf(acc, 0.0f) * w2[j];
    #pragma unroll
    for (int off = 16; off > 0; off >>= 1) z += __shfl_down_sync(0xffffffffu, z, off);
    if ((j & 31) == 0) red[j >> 5] = z;
    __syncthreads();
    if (j == 0) out[b] = red[0] + red[1] + b2[0];
}

// ---------------- launch -----------------------------------------------------
extern "C" void kernel_launch(void* const* d_in, const int* in_sizes, int n_in,
                              void* d_out, int out_size) {
    const float* x     = (const float*)d_in[0];
    const float* w_ih0 = (const float*)d_in[1];
    const float* w_hh0 = (const float*)d_in[2];
    const float* b_ih0 = (const float*)d_in[3];
    const float* b_hh0 = (const float*)d_in[4];
    const float* w_ih1 = (const float*)d_in[5];
    const float* w_hh1 = (const float*)d_in[6];
    const float* b_ih1 = (const float*)d_in[7];
    const float* b_hh1 = (const float*)d_in[8];
    const float* fc1_w = (const float*)d_in[9];
    const float* fc1_b = (const float*)d_in[10];
    const float* fc2_w = (const float*)d_in[11];
    const float* fc2_b = (const float*)d_in[12];
    float* out = (float*)d_out;

    const int smem_rec0 = 163840 + 20480 + 4352;   // 188672
    cudaFuncSetAttribute(k_rec0, cudaFuncAttributeMaxDynamicSharedMemorySize, smem_rec0);

    k_convert<<<(BATCH * TSTEPS * IDIM + 255) / 256, 256>>>(
        x, w_ih0, w_hh0, b_ih0, b_hh0, w_ih1, w_hh1, b_ih1, b_hh1);
    // layer 0: fused input-GEMM + recurrence (writes g_h0), 128 CTAs
    k_rec0<<<BATCH / 4, 512, smem_rec0>>>();
    // xg1 = h0 @ w_ih1^T + bsum1 (writes g_xg), 16-row chunks
    k_gemmh<<<1024, 512>>>();
    // layer-1 recurrence (writes g_h1last), 128 CTAs
    k_rec1<<<BATCH / 4, 512>>>();
    // FC head
    k_fc<<<BATCH, 64>>>(fc1_w, fc1_b, fc2_w, fc2_b, out);
}

// round 17
// speedup vs baseline: 1.2598x; 1.0221x over previous
#include <cuda_runtime.h>
#include <cuda_fp16.h>

#define BATCH  512
#define TSTEPS 256
#define IDIM   32
#define HDIM   128
#define GDIM   512                    // 4*H
#define MROWS  (BATCH * TSTEPS)       // 131072
#define GP2    10                     // fp16 gates pitch (halves)

typedef unsigned long long ull;

// ---------------- scratch (static device globals: allocation-free) ----------
__device__ __half g_xg[(size_t)MROWS * GDIM];   // 128 MB fp16, xg1
__device__ __half g_h0[(size_t)MROWS * HDIM];   // 32 MB fp16, layer-0 hidden
__device__ float  g_h1last[BATCH * HDIM];       // last hidden of layer 1
__device__ __half g_whh[2 * GDIM * HDIM];       // fp16 w_hh0, w_hh1
__device__ __half g_wih0[GDIM * IDIM];          // fp16 w_ih0
__device__ __half g_wih1[GDIM * HDIM];          // fp16 w_ih1
__device__ __half g_xh[(size_t)BATCH * TSTEPS * IDIM];  // fp16 x
__device__ float  g_bsum0[GDIM], g_bsum1[GDIM]; // b_ih + b_hh

// ---------------- fast transcendentals ---------------------------------------
__device__ __forceinline__ float ex2f(float x) {
    float y; asm("ex2.approx.f32 %0, %1;" : "=f"(y) : "f"(x)); return y;
}
__device__ __forceinline__ float rcpf(float x) {
    float y; asm("rcp.approx.f32 %0, %1;" : "=f"(y) : "f"(x)); return y;
}
__device__ __forceinline__ float sigmf(float x) {
    return rcpf(1.0f + ex2f(-1.4426950408889634f * x));
}
__device__ __forceinline__ float tanhf_(float x) {
    return 2.0f * sigmf(2.0f * x) - 1.0f;
}

// ---------------- HMMA m16n8k16 fp16->fp32 -----------------------------------
__device__ __forceinline__ void hmma(float* c, const unsigned* a, unsigned b0, unsigned b1) {
    asm volatile("mma.sync.aligned.m16n8k16.row.col.f32.f16.f16.f32 "
        "{%0,%1,%2,%3}, {%4,%5,%6,%7}, {%8,%9}, {%0,%1,%2,%3};"
        : "+f"(c[0]), "+f"(c[1]), "+f"(c[2]), "+f"(c[3])
        : "r"(a[0]), "r"(a[1]), "r"(a[2]), "r"(a[3]), "r"(b0), "r"(b1));
}

// A-fragments, natural row order: warp owns gate rows warp*32..warp*32+31.
template<int LD>
__device__ __forceinline__ void load_afrag(unsigned afr[2][LD == 32 ? 2 : 8][4],
                                           const __half* W, int warp, int g, int tg) {
    const int NKT = (LD == 32) ? 2 : 8;
    #pragma unroll
    for (int mt = 0; mt < 2; mt++) {
        int rbase = warp * 32 + mt * 16;
        #pragma unroll
        for (int kt = 0; kt < NKT; kt++) {
            int kb = kt * 16 + tg * 2;
            afr[mt][kt][0] = *(const unsigned*)&W[(rbase + g)     * LD + kb];
            afr[mt][kt][1] = *(const unsigned*)&W[(rbase + g + 8) * LD + kb];
            afr[mt][kt][2] = *(const unsigned*)&W[(rbase + g)     * LD + kb + 8];
            afr[mt][kt][3] = *(const unsigned*)&W[(rbase + g + 8) * LD + kb + 8];
        }
    }
}

// Store one warp's gate outputs (fp32 accA+accB) to the fp16 gates buffer.
__device__ __forceinline__ void store_gates16(__half* gates, int warp, int g, int tg,
                                              float aA[2][4], float aB[2][4]) {
    #pragma unroll
    for (int mt = 0; mt < 2; mt++) {
        int r = warp * 32 + mt * 16 + g;
        __half2 lo = __floats2half2_rn(aA[mt][0] + aB[mt][0], aA[mt][1] + aB[mt][1]);
        __half2 hi = __floats2half2_rn(aA[mt][2] + aB[mt][2], aA[mt][3] + aB[mt][3]);
        *(__half2*)&gates[r * GP2 + 2 * tg]       = lo;
        *(__half2*)&gates[(r + 8) * GP2 + 2 * tg] = hi;
    }
}

// ---------------- K0: fp16 conversions + bias sums ---------------------------
__global__ void k_convert(const float* __restrict__ x,
                          const float* __restrict__ w_ih0, const float* __restrict__ w_hh0,
                          const float* __restrict__ b_ih0, const float* __restrict__ b_hh0,
                          const float* __restrict__ w_ih1, const float* __restrict__ w_hh1,
                          const float* __restrict__ b_ih1, const float* __restrict__ b_hh1) {
    int i = blockIdx.x * blockDim.x + threadIdx.x;
    if (i < BATCH * TSTEPS * IDIM) g_xh[i] = __float2half(x[i]);
    if (i < GDIM * HDIM) {
        g_whh[i]               = __float2half(w_hh0[i]);
        g_whh[GDIM * HDIM + i] = __float2half(w_hh1[i]);
        g_wih1[i]              = __float2half(w_ih1[i]);
    }
    if (i < GDIM * IDIM) g_wih0[i] = __float2half(w_ih0[i]);
    if (i < GDIM) {
        g_bsum0[i] = b_ih0[i] + b_hh0[i];
        g_bsum1[i] = b_ih1[i] + b_hh1[i];
    }
}

// ---------------- K1: layer-0 fused (input GEMM + recurrence) ----------------
// 128 CTAs x 512 threads; CTA owns 4 batch elems (MMA n-cols 4..7 ride zeros).
// Split HMMA chains; fp16 gates; 2 barriers/step; 1 cell/thread elementwise.
__global__ __launch_bounds__(512, 1) void k_rec0() {
    extern __shared__ char smr[];
    __half* xtile  = (__half*)smr;                  // [ts][8][40] fp16, 163840 B
    __half* gates  = (__half*)(smr + 163840);       // [512][GP2] fp16, 10240 B
    __half* hT     = (__half*)(smr + 174080);       // [2][8][136] fp16, 4352 B

    const int t = threadIdx.x;
    const int warp = t >> 5, lane = t & 31;
    const int g = lane >> 2, tg = lane & 3;
    const size_t cta_b = (size_t)blockIdx.x * 4;

    unsigned ah[2][8][4], ax[2][2][4];
    load_afrag<HDIM>(ah, g_whh, warp, g, tg);
    load_afrag<IDIM>(ax, g_wih0, warp, g, tg);

    // zero x tile (rows b=4..7 stay zero) and both h buffers
    uint4 zz; zz.x = zz.y = zz.z = zz.w = 0u;
    uint4* xd = (uint4*)xtile;                      // row pitch = 5 uint4
    for (int i = t; i < 256 * 8 * 5; i += 512) xd[i] = zz;
    for (int i = t; i < 2 * 8 * 136 / 8; i += 512) ((uint4*)hT)[i] = zz;
    __syncthreads();

    // stage x for 4 batches: [b][ts][32] -> xtile[ts][b][40]
    {
        const uint4* xs = (const uint4*)g_xh;
        for (int i = t; i < 256 * 4 * 4; i += 512) {
            int ts = i >> 4, b = (i >> 2) & 3, q = i & 3;
            xd[(ts * 8 + b) * 5 + q] = xs[(cta_b + b) * 1024 + ts * 4 + q];
        }
    }

    const int eb = t >> 7, u = t & 127;             // elementwise role (512 cells)
    const float bi = g_bsum0[u],       bf = g_bsum0[u + 128];
    const float bg = g_bsum0[u + 256], bo = g_bsum0[u + 384];
    float cstate = 0.f;
    __syncthreads();

    int cur = 0;
    for (int ts = 0; ts < TSTEPS; ts++) {
        float accA[2][4], accB[2][4];
        #pragma unroll
        for (int mt = 0; mt < 2; mt++)
            #pragma unroll
            for (int p = 0; p < 4; p++) { accA[mt][p] = 0.f; accB[mt][p] = 0.f; }

        // x-part (K = 32) -> chain A
        #pragma unroll
        for (int kt = 0; kt < 2; kt++) {
            unsigned b0 = *(const unsigned*)&xtile[(ts * 8 + g) * 40 + kt * 16 + tg * 2];
            unsigned b1 = *(const unsigned*)&xtile[(ts * 8 + g) * 40 + kt * 16 + tg * 2 + 8];
            hmma(accA[0], ax[0][kt], b0, b1);
            hmma(accA[1], ax[1][kt], b0, b1);
        }
        // h-part (K = 128): kt 0..2 -> A, kt 3..7 -> B (balanced 5/5 chains)
        const __half* hc = hT + cur * (8 * 136);
        #pragma unroll
        for (int kt = 0; kt < 8; kt++) {
            unsigned b0 = *(const unsigned*)&hc[g * 136 + kt * 16 + tg * 2];
            unsigned b1 = *(const unsigned*)&hc[g * 136 + kt * 16 + tg * 2 + 8];
            float* dA = (kt < 3) ? accA[0] : accB[0];
            float* dB = (kt < 3) ? accA[1] : accB[1];
            hmma(dA, ah[0][kt], b0, b1);
            hmma(dB, ah[1][kt], b0, b1);
        }
        store_gates16(gates, warp, g, tg, accA, accB);
        __syncthreads();

        // elementwise: one cell (eb, u) per thread
        __half* hn = hT + (cur ^ 1) * (8 * 136);
        {
            int base = u * GP2 + eb;
            float gi = sigmf (__half2float(gates[base])             + bi);
            float gf = sigmf (__half2float(gates[base + 128 * GP2]) + bf);
            float gg = tanhf_(__half2float(gates[base + 256 * GP2]) + bg);
            float go = sigmf (__half2float(gates[base + 384 * GP2]) + bo);
            cstate = gf * cstate + gi * gg;
            float h = go * tanhf_(cstate);
            hn[eb * 136 + u] = __float2half(h);
            g_h0[((cta_b + eb) * TSTEPS + ts) * HDIM + u] = __float2half(h);
        }
        __syncthreads();
        cur ^= 1;
    }
}

// ---------------- K2: xg1 = h0 @ w_ih1^T + bsum1 (HMMA, 16-row chunks) -------
__global__ __launch_bounds__(512, 1) void k_gemmh() {
    __shared__ __half atile[2][16 * 136];           // 2 x 4352 B
    __shared__ __half gtile[16 * 520];              // 16640 B
    const int t = threadIdx.x;
    const int warp = t >> 5, lane = t & 31;
    const int g = lane >> 2, tg = lane & 3;
    const size_t row0 = (size_t)blockIdx.x * 128;

    unsigned afr[2][8][4];
    float bb[2][2];
    #pragma unroll
    for (int mt = 0; mt < 2; mt++) {
        int rbase = warp * 32 + mt * 16;
        #pragma unroll
        for (int kt = 0; kt < 8; kt++) {
            int kb = kt * 16 + tg * 2;
            afr[mt][kt][0] = *(const unsigned*)&g_wih1[(rbase + g)     * HDIM + kb];
            afr[mt][kt][1] = *(const unsigned*)&g_wih1[(rbase + g + 8) * HDIM + kb];
            afr[mt][kt][2] = *(const unsigned*)&g_wih1[(rbase + g)     * HDIM + kb + 8];
            afr[mt][kt][3] = *(const unsigned*)&g_wih1[(rbase + g + 8) * HDIM + kb + 8];
        }
        bb[mt][0] = g_bsum1[rbase + g];
        bb[mt][1] = g_bsum1[rbase + g + 8];
    }

    // load chunk 0 (16 rows x 128 halves = 256 uint4)
    if (t < 256) {
        int r = t >> 4, q = t & 15;
        *(uint4*)&atile[0][r * 136 + q * 8] = *(const uint4*)(g_h0 + (row0 + r) * HDIM + q * 8);
    }
    __syncthreads();

    #pragma unroll 1
    for (int c = 0; c < 8; c++) {                   // 8 chunks of 16 rows
        int buf = c & 1;
        float acc[2][2][4];                         // [mt][ngroup][4]
        #pragma unroll
        for (int mt = 0; mt < 2; mt++)
            #pragma unroll
            for (int ng = 0; ng < 2; ng++)
                #pragma unroll
                for (int p = 0; p < 4; p++) acc[mt][ng][p] = 0.f;

        #pragma unroll
        for (int kt = 0; kt < 8; kt++) {
            unsigned b0a = *(const unsigned*)&atile[buf][g * 136 + kt * 16 + tg * 2];
            unsigned b1a = *(const unsigned*)&atile[buf][g * 136 + kt * 16 + tg * 2 + 8];
            unsigned b0b = *(const unsigned*)&atile[buf][(8 + g) * 136 + kt * 16 + tg * 2];
            unsigned b1b = *(const unsigned*)&atile[buf][(8 + g) * 136 + kt * 16 + tg * 2 + 8];
            hmma(acc[0][0], afr[0][kt], b0a, b1a);
            hmma(acc[0][1], afr[0][kt], b0b, b1b);
            hmma(acc[1][0], afr[1][kt], b0a, b1a);
            hmma(acc[1][1], afr[1][kt], b0b, b1b);
        }

        // prefetch next chunk (safe: buf^1 unused since 2 syncs ago)
        if (c < 7 && t < 256) {
            int r = t >> 4, q = t & 15;
            *(uint4*)&atile[buf ^ 1][r * 136 + q * 8] =
                *(const uint4*)(g_h0 + (row0 + (c + 1) * 16 + r) * HDIM + q * 8);
        }

        // epilogue: transpose through smem (gtile[n][gate])
        #pragma unroll
        for (int mt = 0; mt < 2; mt++) {
            int r = warp * 32 + mt * 16 + g;
            #pragma unroll
            for (int ng = 0; ng < 2; ng++) {
                int n0 = ng * 8 + 2 * tg;
                gtile[n0       * 520 + r]     = __float2half(acc[mt][ng][0] + bb[mt][0]);
                gtile[(n0 + 1) * 520 + r]     = __float2half(acc[mt][ng][1] + bb[mt][0]);
                gtile[n0       * 520 + r + 8] = __float2half(acc[mt][ng][2] + bb[mt][1]);
                gtile[(n0 + 1) * 520 + r + 8] = __float2half(acc[mt][ng][3] + bb[mt][1]);
            }
        }
        __syncthreads();

        // copy out: 16 rows x 512 halves = 1024 uint4, 2 per thread
        #pragma unroll
        for (int i = 0; i < 2; i++) {
            int idx = t + i * 512;
            int n = idx >> 6, off = (idx & 63) * 8;
            uint4 v = *(uint4*)&gtile[n * 520 + off];
            *(uint4*)(g_xg + (row0 + c * 16 + n) * GDIM + off) = v;
        }
        __syncthreads();
    }
}

// ---------------- K3: layer-1 recurrence (split chains, fp16 gates) ----------
__global__ __launch_bounds__(512, 1) void k_rec1() {
    __shared__ __half gates[GDIM * GP2];            // 10240 B
    __shared__ __half hT[2][8 * 136];               // 4352 B

    const int t = threadIdx.x;
    const int warp = t >> 5, lane = t & 31;
    const int g = lane >> 2, tg = lane & 3;
    const size_t cta_b = (size_t)blockIdx.x * 4;

    unsigned ah[2][8][4];
    load_afrag<HDIM>(ah, g_whh + GDIM * HDIM, warp, g, tg);

    uint4 zz; zz.x = zz.y = zz.z = zz.w = 0u;
    for (int i = t; i < 2 * 8 * 136 / 8; i += 512) ((uint4*)hT)[i] = zz;

    const int b = t >> 7, u = t & 127;
    float cstate = 0.f;
    const __half* xbase = g_xg + (cta_b + b) * ((size_t)TSTEPS * GDIM) + u;

    __half xc[4];
    xc[0] = xbase[0]; xc[1] = xbase[128]; xc[2] = xbase[256]; xc[3] = xbase[384];
    __syncthreads();

    int cur = 0;
    for (int ts = 0; ts < TSTEPS; ts++) {
        __half xn[4];
        if (ts < TSTEPS - 1) {
            const __half* xp = xbase + (size_t)(ts + 1) * GDIM;
            xn[0] = xp[0]; xn[1] = xp[128]; xn[2] = xp[256]; xn[3] = xp[384];
        }

        float accA[2][4], accB[2][4];
        #pragma unroll
        for (int mt = 0; mt < 2; mt++)
            #pragma unroll
            for (int p = 0; p < 4; p++) { accA[mt][p] = 0.f; accB[mt][p] = 0.f; }

        // kt 0..3 -> chain A, kt 4..7 -> chain B
        const __half* hc = hT[cur];
        #pragma unroll
        for (int kt = 0; kt < 8; kt++) {
            unsigned b0 = *(const unsigned*)&hc[g * 136 + kt * 16 + tg * 2];
            unsigned b1 = *(const unsigned*)&hc[g * 136 + kt * 16 + tg * 2 + 8];
            float* dA = (kt < 4) ? accA[0] : accB[0];
            float* dB = (kt < 4) ? accA[1] : accB[1];
            hmma(dA, ah[0][kt], b0, b1);
            hmma(dB, ah[1][kt], b0, b1);
        }
        store_gates16(gates, warp, g, tg, accA, accB);
        __syncthreads();

        __half* hn = hT[cur ^ 1];
        {
            int base = u * GP2 + b;
            float gi = sigmf (__half2float(gates[base])             + __half2float(xc[0]));
            float gf = sigmf (__half2float(gates[base + 128 * GP2]) + __half2float(xc[1]));
            float gg = tanhf_(__half2float(gates[base + 256 * GP2]) + __half2float(xc[2]));
            float go = sigmf (__half2float(gates[base + 384 * GP2]) + __half2float(xc[3]));
            cstate = gf * cstate + gi * gg;
            float h = go * tanhf_(cstate);
            hn[b * 136 + u] = __float2half(h);
            if (ts == TSTEPS - 1)
                g_h1last[(cta_b + b) * HDIM + u] = h;
        }
        __syncthreads();

        xc[0] = xn[0]; xc[1] = xn[1]; xc[2] = xn[2]; xc[3] = xn[3];
        cur ^= 1;
    }
}

// ---------------- K4: FC head (ILP) ------------------------------------------
__global__ void k_fc(const float* __restrict__ w1, const float* __restrict__ b1,
                     const float* __restrict__ w2, const float* __restrict__ b2,
                     float* __restrict__ out) {
    __shared__ float red[2];
    int b = blockIdx.x, j = threadIdx.x;   // 64 threads
    const float4* hv = (const float4*)(g_h1last + b * HDIM);
    const float4* wr = (const float4*)(w1 + j * HDIM);
    float a0 = 0.f, a1 = 0.f, a2 = 0.f, a3 = 0.f;
    #pragma unroll
    for (int k = 0; k < 32; k += 2) {
        float4 h0 = hv[k],     w0 = wr[k];
        float4 h1 = hv[k + 1], w1v = wr[k + 1];
        a0 += h0.x * w0.x + h0.y * w0.y;
        a1 += h0.z * w0.z + h0.w * w0.w;
        a2 += h1.x * w1v.x + h1.y * w1v.y;
        a3 += h1.z * w1v.z + h1.w * w1v.w;
    }
    float acc = ((a0 + a1) + (a2 + a3)) + b1[j];
    float z = fmaxf(acc, 0.0f) * w2[j];
    #pragma unroll
    for (int off = 16; off > 0; off >>= 1) z += __shfl_down_sync(0xffffffffu, z, off);
    if ((j & 31) == 0) red[j >> 5] = z;
    __syncthreads();
    if (j == 0) out[b] = red[0] + red[1] + b2[0];
}

// ---------------- launch -----------------------------------------------------
extern "C" void kernel_launch(void* const* d_in, const int* in_sizes, int n_in,
                              void* d_out, int out_size) {
    const float* x     = (const float*)d_in[0];
    const float* w_ih0 = (const float*)d_in[1];
    const float* w_hh0 = (const float*)d_in[2];
    const float* b_ih0 = (const float*)d_in[3];
    const float* b_hh0 = (const float*)d_in[4];
    const float* w_ih1 = (const float*)d_in[5];
    const float* w_hh1 = (const float*)d_in[6];
    const float* b_ih1 = (const float*)d_in[7];
    const float* b_hh1 = (const float*)d_in[8];
    const float* fc1_w = (const float*)d_in[9];
    const float* fc1_b = (const float*)d_in[10];
    const float* fc2_w = (const float*)d_in[11];
    const float* fc2_b = (const float*)d_in[12];
    float* out = (float*)d_out;

    const int smem_rec0 = 163840 + 10240 + 4352;   // 178432
    cudaFuncSetAttribute(k_rec0, cudaFuncAttributeMaxDynamicSharedMemorySize, smem_rec0);

    k_convert<<<(BATCH * TSTEPS * IDIM + 255) / 256, 256>>>(
        x, w_ih0, w_hh0, b_ih0, b_hh0, w_ih1, w_hh1, b_ih1, b_hh1);
    // layer 0: fused input-GEMM + recurrence (writes g_h0), 128 CTAs
    k_rec0<<<BATCH / 4, 512, smem_rec0>>>();
    // xg1 = h0 @ w_ih1^T + bsum1 (writes g_xg), 16-row chunks
    k_gemmh<<<1024, 512>>>();
    // layer-1 recurrence (writes g_h1last), 128 CTAs
    k_rec1<<<BATCH / 4, 512>>>();
    // FC head
    k_fc<<<BATCH, 64>>>(fc1_w, fc1_b, fc2_w, fc2_b, out);
}